// round 1
// baseline (speedup 1.0000x reference)
#include <cuda_runtime.h>

// Problem dims
#define BATCH 4
#define SEQ   2048
#define DSEQ  1024      // model dim
#define HEADS 16
#define DHEAD 64
#define DINNER 1024     // HEADS*DHEAD
#define MROWS (BATCH*SEQ)   // 8192
#define NQKV  (3*DINNER)    // 3072

// Scratch (allocation-free: __device__ globals)
__device__ float g_Q[BATCH * HEADS * SEQ * DHEAD];   // [b,h,n,d]
__device__ float g_K[BATCH * HEADS * SEQ * DHEAD];
__device__ float g_V[BATCH * HEADS * SEQ * DHEAD];
__device__ float g_AO[MROWS * DINNER];               // [b,n,h*d]

// ---------------------------------------------------------------------------
// GEMM 1: qkv = x @ w_qkv^T, scattered into head-major Q/K/V.
// x: [8192,1024] row-major. w: [3072,1024] row-major. BM=BN=64, BK=16.
// 256 threads, 4x4 micro-tile per thread. A block's 64 output columns span
// exactly one (part, head) pair since 64 | 1024.
// ---------------------------------------------------------------------------
__global__ __launch_bounds__(256) void qkv_gemm(const float* __restrict__ x,
                                                const float* __restrict__ w) {
    __shared__ float As[16 * 64];   // [k][m] transposed
    __shared__ float Bs[16 * 64];   // [k][n] transposed

    const int t  = threadIdx.x;
    const int tx = t & 15;
    const int ty = t >> 4;
    const int n0 = blockIdx.x * 64;
    const int m0 = blockIdx.y * 64;

    const int lrow = t >> 2;          // 0..63
    const int lkv  = (t & 3) * 4;     // 0,4,8,12
    const float* xg = x + (size_t)(m0 + lrow) * DSEQ + lkv;
    const float* wg = w + (size_t)(n0 + lrow) * DSEQ + lkv;

    float acc[4][4] = {};

    for (int k0 = 0; k0 < DSEQ; k0 += 16) {
        float4 av = *(const float4*)(xg + k0);
        float4 bv = *(const float4*)(wg + k0);
        __syncthreads();
        As[(lkv + 0) * 64 + lrow] = av.x;
        As[(lkv + 1) * 64 + lrow] = av.y;
        As[(lkv + 2) * 64 + lrow] = av.z;
        As[(lkv + 3) * 64 + lrow] = av.w;
        Bs[(lkv + 0) * 64 + lrow] = bv.x;
        Bs[(lkv + 1) * 64 + lrow] = bv.y;
        Bs[(lkv + 2) * 64 + lrow] = bv.z;
        Bs[(lkv + 3) * 64 + lrow] = bv.w;
        __syncthreads();
#pragma unroll
        for (int kk = 0; kk < 16; kk++) {
            float4 a = *(const float4*)&As[kk * 64 + ty * 4];
            float4 b = *(const float4*)&Bs[kk * 64 + tx * 4];
            acc[0][0] += a.x * b.x; acc[0][1] += a.x * b.y; acc[0][2] += a.x * b.z; acc[0][3] += a.x * b.w;
            acc[1][0] += a.y * b.x; acc[1][1] += a.y * b.y; acc[1][2] += a.y * b.z; acc[1][3] += a.y * b.w;
            acc[2][0] += a.z * b.x; acc[2][1] += a.z * b.y; acc[2][2] += a.z * b.z; acc[2][3] += a.z * b.w;
            acc[3][0] += a.w * b.x; acc[3][1] += a.w * b.y; acc[3][2] += a.w * b.z; acc[3][3] += a.w * b.w;
        }
    }

    const int part = n0 >> 10;               // 0=Q 1=K 2=V
    const int h    = (n0 & 1023) >> 6;
    float* Tp = (part == 0) ? g_Q : (part == 1) ? g_K : g_V;
    const int dd = tx * 4;
#pragma unroll
    for (int i = 0; i < 4; i++) {
        int m = m0 + ty * 4 + i;
        int b = m >> 11;          // /2048
        int n = m & 2047;
        float4 v = make_float4(acc[i][0], acc[i][1], acc[i][2], acc[i][3]);
        *(float4*)&Tp[(((size_t)(b * HEADS + h)) * SEQ + n) * DHEAD + dd] = v;
    }
}

// ---------------------------------------------------------------------------
// Flash attention. One block per (bh, 64-query tile). 256 threads, 4x4
// micro-tiles for both S = Q K^T and O += P V. Online softmax with 16-lane
// shuffle reductions (threads sharing a row are 16 contiguous lanes).
// Dynamic smem: Qs[64][64] (transposed [d][i]) | Ks[64][64] ([d][j]) unioned
// with Ps[64][68] ([j][i]) | Vs[64][64] ([j][c]).
// ---------------------------------------------------------------------------
#define ATTN_SMEM_FLOATS (4096 + 64 * 68 + 4096)
#define ATTN_SMEM_BYTES  (ATTN_SMEM_FLOATS * 4)

__global__ __launch_bounds__(256) void attn_kernel() {
    extern __shared__ float sm[];
    float* Qs = sm;                  // stride 64
    float* Ks = sm + 4096;           // stride 64
    float* Ps = sm + 4096;           // stride 68 (union with Ks)
    float* Vs = sm + 4096 + 64 * 68; // stride 64

    const int t  = threadIdx.x;
    const int tx = t & 15;
    const int ty = t >> 4;
    const int bh = blockIdx.y;
    const int q0 = blockIdx.x * 64;

    const size_t base = (size_t)bh * SEQ * DHEAD;
    const float* Qg = g_Q + base;
    const float* Kg = g_K + base;
    const float* Vg = g_V + base;

    const int lr = t >> 2;          // 0..63
    const int ls = (t & 3) * 16;    // d/col segment

    // Load Q tile transposed, pre-scaled by 1/sqrt(d)
    {
        const float* src = Qg + (size_t)(q0 + lr) * DHEAD + ls;
#pragma unroll
        for (int q = 0; q < 4; q++) {
            float4 v = *(const float4*)(src + q * 4);
            int d = ls + q * 4;
            Qs[(d + 0) * 64 + lr] = v.x * 0.125f;
            Qs[(d + 1) * 64 + lr] = v.y * 0.125f;
            Qs[(d + 2) * 64 + lr] = v.z * 0.125f;
            Qs[(d + 3) * 64 + lr] = v.w * 0.125f;
        }
    }

    float acc[4][4] = {};
    float mrow[4] = {-1e30f, -1e30f, -1e30f, -1e30f};
    float lrowv[4] = {0.f, 0.f, 0.f, 0.f};

    for (int kv0 = 0; kv0 < SEQ; kv0 += 64) {
        __syncthreads();   // previous PV done reading Ps/Vs; Q load done (1st iter)
        {
            const float* ksrc = Kg + (size_t)(kv0 + lr) * DHEAD + ls;
#pragma unroll
            for (int q = 0; q < 4; q++) {
                float4 v = *(const float4*)(ksrc + q * 4);
                int d = ls + q * 4;
                Ks[(d + 0) * 64 + lr] = v.x;
                Ks[(d + 1) * 64 + lr] = v.y;
                Ks[(d + 2) * 64 + lr] = v.z;
                Ks[(d + 3) * 64 + lr] = v.w;
            }
            const float* vsrc = Vg + (size_t)(kv0 + lr) * DHEAD + ls;
#pragma unroll
            for (int q = 0; q < 4; q++) {
                *(float4*)&Vs[lr * 64 + ls + q * 4] = *(const float4*)(vsrc + q * 4);
            }
        }
        __syncthreads();

        // S = (Q*scale) K^T, 4x4 per thread
        float s[4][4] = {};
#pragma unroll 8
        for (int d = 0; d < 64; d++) {
            float4 a = *(const float4*)&Qs[d * 64 + ty * 4];
            float4 b = *(const float4*)&Ks[d * 64 + tx * 4];
            s[0][0] += a.x * b.x; s[0][1] += a.x * b.y; s[0][2] += a.x * b.z; s[0][3] += a.x * b.w;
            s[1][0] += a.y * b.x; s[1][1] += a.y * b.y; s[1][2] += a.y * b.z; s[1][3] += a.y * b.w;
            s[2][0] += a.z * b.x; s[2][1] += a.z * b.y; s[2][2] += a.z * b.z; s[2][3] += a.z * b.w;
            s[3][0] += a.w * b.x; s[3][1] += a.w * b.y; s[3][2] += a.w * b.z; s[3][3] += a.w * b.w;
        }

        // Online softmax: row stats across 16 lanes sharing a row
        float alpha[4];
#pragma unroll
        for (int i = 0; i < 4; i++) {
            float mx = fmaxf(fmaxf(s[i][0], s[i][1]), fmaxf(s[i][2], s[i][3]));
#pragma unroll
            for (int off = 8; off >= 1; off >>= 1)
                mx = fmaxf(mx, __shfl_xor_sync(0xffffffffu, mx, off));
            float mnew = fmaxf(mrow[i], mx);
            alpha[i] = __expf(mrow[i] - mnew);
            mrow[i] = mnew;
            float rs = 0.f;
#pragma unroll
            for (int j = 0; j < 4; j++) {
                s[i][j] = __expf(s[i][j] - mnew);
                rs += s[i][j];
            }
#pragma unroll
            for (int off = 8; off >= 1; off >>= 1)
                rs += __shfl_xor_sync(0xffffffffu, rs, off);
            lrowv[i] = lrowv[i] * alpha[i] + rs;
#pragma unroll
            for (int j = 0; j < 4; j++) acc[i][j] *= alpha[i];
        }

        __syncthreads();   // everyone done reading Ks before Ps overwrite
        // Write P transposed: Ps[j][i]
#pragma unroll
        for (int j = 0; j < 4; j++) {
            int jg = tx * 4 + j;
            *(float4*)&Ps[jg * 68 + ty * 4] = make_float4(s[0][j], s[1][j], s[2][j], s[3][j]);
        }
        __syncthreads();

        // O += P V
#pragma unroll 8
        for (int jg = 0; jg < 64; jg++) {
            float4 a = *(const float4*)&Ps[jg * 68 + ty * 4];
            float4 b = *(const float4*)&Vs[jg * 64 + tx * 4];
            acc[0][0] += a.x * b.x; acc[0][1] += a.x * b.y; acc[0][2] += a.x * b.z; acc[0][3] += a.x * b.w;
            acc[1][0] += a.y * b.x; acc[1][1] += a.y * b.y; acc[1][2] += a.y * b.z; acc[1][3] += a.y * b.w;
            acc[2][0] += a.z * b.x; acc[2][1] += a.z * b.y; acc[2][2] += a.z * b.z; acc[2][3] += a.z * b.w;
            acc[3][0] += a.w * b.x; acc[3][1] += a.w * b.y; acc[3][2] += a.w * b.z; acc[3][3] += a.w * b.w;
        }
    }

    // Epilogue: normalize and write to g_AO [b, n, h*64 + c]
    const int b = bh >> 4;
    const int h = bh & 15;
#pragma unroll
    for (int i = 0; i < 4; i++) {
        int row = q0 + ty * 4 + i;
        float inv = 1.0f / lrowv[i];
        float4 v = make_float4(acc[i][0] * inv, acc[i][1] * inv, acc[i][2] * inv, acc[i][3] * inv);
        *(float4*)&g_AO[((size_t)(b * SEQ + row)) * DINNER + h * 64 + tx * 4] = v;
    }
}

// ---------------------------------------------------------------------------
// GEMM 2: out = AO @ w_out^T + b_out. Same tiling as GEMM 1.
// ---------------------------------------------------------------------------
__global__ __launch_bounds__(256) void out_gemm(const float* __restrict__ w,
                                                const float* __restrict__ bias,
                                                float* __restrict__ out) {
    __shared__ float As[16 * 64];
    __shared__ float Bs[16 * 64];

    const int t  = threadIdx.x;
    const int tx = t & 15;
    const int ty = t >> 4;
    const int n0 = blockIdx.x * 64;
    const int m0 = blockIdx.y * 64;

    const int lrow = t >> 2;
    const int lkv  = (t & 3) * 4;
    const float* xg = g_AO + (size_t)(m0 + lrow) * DINNER + lkv;
    const float* wg = w + (size_t)(n0 + lrow) * DINNER + lkv;

    float acc[4][4] = {};

    for (int k0 = 0; k0 < DINNER; k0 += 16) {
        float4 av = *(const float4*)(xg + k0);
        float4 bv = *(const float4*)(wg + k0);
        __syncthreads();
        As[(lkv + 0) * 64 + lrow] = av.x;
        As[(lkv + 1) * 64 + lrow] = av.y;
        As[(lkv + 2) * 64 + lrow] = av.z;
        As[(lkv + 3) * 64 + lrow] = av.w;
        Bs[(lkv + 0) * 64 + lrow] = bv.x;
        Bs[(lkv + 1) * 64 + lrow] = bv.y;
        Bs[(lkv + 2) * 64 + lrow] = bv.z;
        Bs[(lkv + 3) * 64 + lrow] = bv.w;
        __syncthreads();
#pragma unroll
        for (int kk = 0; kk < 16; kk++) {
            float4 a = *(const float4*)&As[kk * 64 + ty * 4];
            float4 b = *(const float4*)&Bs[kk * 64 + tx * 4];
            acc[0][0] += a.x * b.x; acc[0][1] += a.x * b.y; acc[0][2] += a.x * b.z; acc[0][3] += a.x * b.w;
            acc[1][0] += a.y * b.x; acc[1][1] += a.y * b.y; acc[1][2] += a.y * b.z; acc[1][3] += a.y * b.w;
            acc[2][0] += a.z * b.x; acc[2][1] += a.z * b.y; acc[2][2] += a.z * b.z; acc[2][3] += a.z * b.w;
            acc[3][0] += a.w * b.x; acc[3][1] += a.w * b.y; acc[3][2] += a.w * b.z; acc[3][3] += a.w * b.w;
        }
    }

    const int c = n0 + tx * 4;
    float4 bv4 = *(const float4*)&bias[c];
#pragma unroll
    for (int i = 0; i < 4; i++) {
        int m = m0 + ty * 4 + i;
        float4 v = make_float4(acc[i][0] + bv4.x, acc[i][1] + bv4.y,
                               acc[i][2] + bv4.z, acc[i][3] + bv4.w);
        *(float4*)&out[(size_t)m * DSEQ + c] = v;
    }
}

// ---------------------------------------------------------------------------
extern "C" void kernel_launch(void* const* d_in, const int* in_sizes, int n_in,
                              void* d_out, int out_size) {
    const float* x     = (const float*)d_in[0];
    const float* w_qkv = (const float*)d_in[1];
    const float* w_out = (const float*)d_in[2];
    const float* b_out = (const float*)d_in[3];
    float* out = (float*)d_out;

    // Allow >48KB dynamic smem for the attention kernel (idempotent, no alloc)
    cudaFuncSetAttribute(attn_kernel, cudaFuncAttributeMaxDynamicSharedMemorySize,
                         ATTN_SMEM_BYTES);

    qkv_gemm<<<dim3(NQKV / 64, MROWS / 64), 256>>>(x, w_qkv);
    attn_kernel<<<dim3(SEQ / 64, BATCH * HEADS), 256, ATTN_SMEM_BYTES>>>();
    out_gemm<<<dim3(DSEQ / 64, MROWS / 64), 256>>>(w_out, b_out, out);
}

// round 2
// speedup vs baseline: 2.6179x; 2.6179x over previous
#include <cuda_runtime.h>

// Problem dims
#define BATCH 4
#define SEQ   2048
#define DSEQ  1024
#define HEADS 16
#define DHEAD 64
#define DINNER 1024
#define MROWS (BATCH*SEQ)   // 8192
#define NQKV  (3*DINNER)    // 3072

// Scratch (allocation-free: __device__ globals)
__device__ float g_Q[BATCH * HEADS * SEQ * DHEAD];   // [b,h,n,d]
__device__ float g_K[BATCH * HEADS * SEQ * DHEAD];
__device__ float g_V[BATCH * HEADS * SEQ * DHEAD];
__device__ float g_AO[MROWS * DINNER];               // [b,n,h*d]

// ---------------------------------------------------------------------------
// tf32 helpers
// ---------------------------------------------------------------------------
__device__ __forceinline__ float f2tf(float f) {
    unsigned u;
    asm("cvt.rna.tf32.f32 %0, %1;" : "=r"(u) : "f"(f));
    return __uint_as_float(u);
}

__device__ __forceinline__ void mma_tf32(float c[4],
                                         unsigned a0, unsigned a1, unsigned a2, unsigned a3,
                                         unsigned b0, unsigned b1) {
    asm volatile(
        "mma.sync.aligned.m16n8k8.row.col.f32.tf32.tf32.f32 "
        "{%0,%1,%2,%3},{%4,%5,%6,%7},{%8,%9},{%0,%1,%2,%3};"
        : "+f"(c[0]), "+f"(c[1]), "+f"(c[2]), "+f"(c[3])
        : "r"(a0), "r"(a1), "r"(a2), "r"(a3), "r"(b0), "r"(b1));
}

#define FB(x) __float_as_uint(x)

// ---------------------------------------------------------------------------
// GEMM core: D = X[M,K] @ W[N,K]^T using m16n8k8 tf32 mma.
// BM=128, BN=128, BK=16, 256 threads (8 warps: 2 in m x 4 in n).
// Warp tile 64x32 = 4 m16-tiles x 4 n8-tiles. tf32 conversion at smem store.
// ---------------------------------------------------------------------------
#define GST 17   // smem row stride (16 + 1 pad)

// epilogue mode: 0 = scatter to Q/K/V, 1 = write out + bias
__global__ __launch_bounds__(256) void qkv_gemm(const float* __restrict__ x,
                                                const float* __restrict__ w) {
    __shared__ float As[128 * GST];
    __shared__ float Bs[128 * GST];

    const int t    = threadIdx.x;
    const int lane = t & 31;
    const int wp   = t >> 5;
    const int g    = lane >> 2;
    const int tg   = lane & 3;
    const int wm   = wp & 1;        // 0..1
    const int wn   = wp >> 1;       // 0..3
    const int m0   = blockIdx.y * 128;
    const int n0   = blockIdx.x * 128;

    float c[4][4][4] = {};

    for (int k0 = 0; k0 < DSEQ; k0 += 16) {
        float4 av[2], bv[2];
#pragma unroll
        for (int i = 0; i < 2; i++) {
            int f = t * 2 + i;
            int row = f >> 2, ks = (f & 3) * 4;
            av[i] = *(const float4*)&x[(size_t)(m0 + row) * DSEQ + k0 + ks];
            bv[i] = *(const float4*)&w[(size_t)(n0 + row) * DSEQ + k0 + ks];
        }
        __syncthreads();
#pragma unroll
        for (int i = 0; i < 2; i++) {
            int f = t * 2 + i;
            int row = f >> 2, ks = (f & 3) * 4;
            As[row * GST + ks + 0] = f2tf(av[i].x);
            As[row * GST + ks + 1] = f2tf(av[i].y);
            As[row * GST + ks + 2] = f2tf(av[i].z);
            As[row * GST + ks + 3] = f2tf(av[i].w);
            Bs[row * GST + ks + 0] = f2tf(bv[i].x);
            Bs[row * GST + ks + 1] = f2tf(bv[i].y);
            Bs[row * GST + ks + 2] = f2tf(bv[i].z);
            Bs[row * GST + ks + 3] = f2tf(bv[i].w);
        }
        __syncthreads();

#pragma unroll
        for (int kk = 0; kk < 2; kk++) {
            const int k = kk * 8;
            unsigned a[4][4], b[4][2];
#pragma unroll
            for (int mt = 0; mt < 4; mt++) {
                const float* ap = &As[(wm * 64 + mt * 16 + g) * GST + k + tg];
                a[mt][0] = FB(ap[0]);
                a[mt][1] = FB(ap[8 * GST]);
                a[mt][2] = FB(ap[4]);
                a[mt][3] = FB(ap[8 * GST + 4]);
            }
#pragma unroll
            for (int nt = 0; nt < 4; nt++) {
                const float* bp = &Bs[(wn * 32 + nt * 8 + g) * GST + k + tg];
                b[nt][0] = FB(bp[0]);
                b[nt][1] = FB(bp[4]);
            }
#pragma unroll
            for (int mt = 0; mt < 4; mt++)
#pragma unroll
                for (int nt = 0; nt < 4; nt++)
                    mma_tf32(c[mt][nt], a[mt][0], a[mt][1], a[mt][2], a[mt][3],
                             b[nt][0], b[nt][1]);
        }
    }

    // Scatter epilogue into head-major Q/K/V
#pragma unroll
    for (int mt = 0; mt < 4; mt++) {
#pragma unroll
        for (int nt = 0; nt < 4; nt++) {
            int col  = n0 + wn * 32 + nt * 8 + tg * 2;
            int part = col >> 10;
            int h    = (col >> 6) & 15;
            int d    = col & 63;
            float* Tp = (part == 0) ? g_Q : (part == 1) ? g_K : g_V;
            int m  = m0 + wm * 64 + mt * 16 + g;
            int b  = m >> 11, n = m & 2047;
            *(float2*)&Tp[(((size_t)(b * HEADS + h)) * SEQ + n) * DHEAD + d] =
                make_float2(c[mt][nt][0], c[mt][nt][1]);
            int m2 = m + 8;
            int b2 = m2 >> 11, n2 = m2 & 2047;
            *(float2*)&Tp[(((size_t)(b2 * HEADS + h)) * SEQ + n2) * DHEAD + d] =
                make_float2(c[mt][nt][2], c[mt][nt][3]);
        }
    }
}

__global__ __launch_bounds__(256) void out_gemm(const float* __restrict__ w,
                                                const float* __restrict__ bias,
                                                float* __restrict__ out) {
    __shared__ float As[128 * GST];
    __shared__ float Bs[128 * GST];

    const int t    = threadIdx.x;
    const int lane = t & 31;
    const int wp   = t >> 5;
    const int g    = lane >> 2;
    const int tg   = lane & 3;
    const int wm   = wp & 1;
    const int wn   = wp >> 1;
    const int m0   = blockIdx.y * 128;
    const int n0   = blockIdx.x * 128;

    float c[4][4][4] = {};

    for (int k0 = 0; k0 < DINNER; k0 += 16) {
        float4 av[2], bv[2];
#pragma unroll
        for (int i = 0; i < 2; i++) {
            int f = t * 2 + i;
            int row = f >> 2, ks = (f & 3) * 4;
            av[i] = *(const float4*)&g_AO[(size_t)(m0 + row) * DINNER + k0 + ks];
            bv[i] = *(const float4*)&w[(size_t)(n0 + row) * DINNER + k0 + ks];
        }
        __syncthreads();
#pragma unroll
        for (int i = 0; i < 2; i++) {
            int f = t * 2 + i;
            int row = f >> 2, ks = (f & 3) * 4;
            As[row * GST + ks + 0] = f2tf(av[i].x);
            As[row * GST + ks + 1] = f2tf(av[i].y);
            As[row * GST + ks + 2] = f2tf(av[i].z);
            As[row * GST + ks + 3] = f2tf(av[i].w);
            Bs[row * GST + ks + 0] = f2tf(bv[i].x);
            Bs[row * GST + ks + 1] = f2tf(bv[i].y);
            Bs[row * GST + ks + 2] = f2tf(bv[i].z);
            Bs[row * GST + ks + 3] = f2tf(bv[i].w);
        }
        __syncthreads();

#pragma unroll
        for (int kk = 0; kk < 2; kk++) {
            const int k = kk * 8;
            unsigned a[4][4], b[4][2];
#pragma unroll
            for (int mt = 0; mt < 4; mt++) {
                const float* ap = &As[(wm * 64 + mt * 16 + g) * GST + k + tg];
                a[mt][0] = FB(ap[0]);
                a[mt][1] = FB(ap[8 * GST]);
                a[mt][2] = FB(ap[4]);
                a[mt][3] = FB(ap[8 * GST + 4]);
            }
#pragma unroll
            for (int nt = 0; nt < 4; nt++) {
                const float* bp = &Bs[(wn * 32 + nt * 8 + g) * GST + k + tg];
                b[nt][0] = FB(bp[0]);
                b[nt][1] = FB(bp[4]);
            }
#pragma unroll
            for (int mt = 0; mt < 4; mt++)
#pragma unroll
                for (int nt = 0; nt < 4; nt++)
                    mma_tf32(c[mt][nt], a[mt][0], a[mt][1], a[mt][2], a[mt][3],
                             b[nt][0], b[nt][1]);
        }
    }

#pragma unroll
    for (int mt = 0; mt < 4; mt++) {
#pragma unroll
        for (int nt = 0; nt < 4; nt++) {
            int col = n0 + wn * 32 + nt * 8 + tg * 2;
            float bx = bias[col], by = bias[col + 1];
            int m = m0 + wm * 64 + mt * 16 + g;
            *(float2*)&out[(size_t)m * DSEQ + col] =
                make_float2(c[mt][nt][0] + bx, c[mt][nt][1] + by);
            *(float2*)&out[(size_t)(m + 8) * DSEQ + col] =
                make_float2(c[mt][nt][2] + bx, c[mt][nt][3] + by);
        }
    }
}

// ---------------------------------------------------------------------------
// Flash attention with tf32 mma. Block = 256 threads (8 warps), Q-tile = 128
// rows, KV-tile = 64. Each warp owns 16 query rows (all 8 warps stacked in m),
// so softmax rows reduce with intra-warp shuffles only.
// smem: Qs[128][68] | KP[128][68] (Ks 64 rows, reused as Ps 128 rows) | Vs[64][68] (transposed [d][j])
// ---------------------------------------------------------------------------
#define AST 68
#define ATTN_SMEM_BYTES ((128 + 128 + 64) * AST * 4)

__global__ __launch_bounds__(256) void attn_kernel() {
    extern __shared__ float sm[];
    float* Qs = sm;                   // [128][AST] (m, d)
    float* KP = sm + 128 * AST;       // Ks: [64][AST] (j, d); Ps: [128][AST] (m, j)
    float* Vs = sm + 256 * AST;       // [64][AST]  (d, j)  -- transposed

    const int t    = threadIdx.x;
    const int lane = t & 31;
    const int wp   = t >> 5;
    const int g    = lane >> 2;
    const int tg   = lane & 3;
    const int bh   = blockIdx.y;
    const int q0   = blockIdx.x * 128;

    const size_t base = (size_t)bh * SEQ * DHEAD;
    const float* Qg = g_Q + base;
    const float* Kg = g_K + base;
    const float* Vg = g_V + base;

    // Load Q tile, pre-scaled by 1/sqrt(64), tf32-rounded
    {
        int row = t >> 1, seg = (t & 1) * 32;
        const float* src = Qg + (size_t)(q0 + row) * DHEAD + seg;
        float* dst = &Qs[row * AST + seg];
#pragma unroll
        for (int i = 0; i < 8; i++) {
            float4 v = *(const float4*)(src + i * 4);
            dst[i * 4 + 0] = f2tf(v.x * 0.125f);
            dst[i * 4 + 1] = f2tf(v.y * 0.125f);
            dst[i * 4 + 2] = f2tf(v.z * 0.125f);
            dst[i * 4 + 3] = f2tf(v.w * 0.125f);
        }
    }

    float mi[2] = {-1e30f, -1e30f};
    float li[2] = {0.f, 0.f};
    float of[8][4] = {};

    const int krow = t >> 2;          // 0..63
    const int kseg = (t & 3) * 16;

    for (int kv0 = 0; kv0 < SEQ; kv0 += 64) {
        __syncthreads();  // prior PV reads of KP/Vs done; Q load done (iter 0)
        {
            const float* ks = Kg + (size_t)(kv0 + krow) * DHEAD + kseg;
            const float* vs = Vg + (size_t)(kv0 + krow) * DHEAD + kseg;
            float* kd = &KP[krow * AST + kseg];
#pragma unroll
            for (int i = 0; i < 4; i++) {
                float4 v = *(const float4*)(ks + i * 4);
                kd[i * 4 + 0] = f2tf(v.x);
                kd[i * 4 + 1] = f2tf(v.y);
                kd[i * 4 + 2] = f2tf(v.z);
                kd[i * 4 + 3] = f2tf(v.w);
                float4 u = *(const float4*)(vs + i * 4);
                Vs[(kseg + i * 4 + 0) * AST + krow] = f2tf(u.x);
                Vs[(kseg + i * 4 + 1) * AST + krow] = f2tf(u.y);
                Vs[(kseg + i * 4 + 2) * AST + krow] = f2tf(u.z);
                Vs[(kseg + i * 4 + 3) * AST + krow] = f2tf(u.w);
            }
        }
        __syncthreads();

        // S = Q K^T : warp rows wp*16, all 64 cols
        float sc[8][4] = {};
#pragma unroll
        for (int kk = 0; kk < 8; kk++) {
            const int k = kk * 8;
            const float* ap = &Qs[(wp * 16 + g) * AST + k + tg];
            unsigned a0 = FB(ap[0]), a1 = FB(ap[8 * AST]);
            unsigned a2 = FB(ap[4]), a3 = FB(ap[8 * AST + 4]);
#pragma unroll
            for (int nt = 0; nt < 8; nt++) {
                const float* bp = &KP[(nt * 8 + g) * AST + k + tg];
                mma_tf32(sc[nt], a0, a1, a2, a3, FB(bp[0]), FB(bp[4]));
            }
        }

        // Online softmax (rows g and g+8 of this warp's 16)
        float mx0 = -1e30f, mx1 = -1e30f;
#pragma unroll
        for (int nt = 0; nt < 8; nt++) {
            mx0 = fmaxf(mx0, fmaxf(sc[nt][0], sc[nt][1]));
            mx1 = fmaxf(mx1, fmaxf(sc[nt][2], sc[nt][3]));
        }
#pragma unroll
        for (int off = 1; off <= 2; off <<= 1) {
            mx0 = fmaxf(mx0, __shfl_xor_sync(0xffffffffu, mx0, off));
            mx1 = fmaxf(mx1, __shfl_xor_sync(0xffffffffu, mx1, off));
        }
        float mn0 = fmaxf(mi[0], mx0), mn1 = fmaxf(mi[1], mx1);
        float al0 = __expf(mi[0] - mn0), al1 = __expf(mi[1] - mn1);
        mi[0] = mn0; mi[1] = mn1;
        float rs0 = 0.f, rs1 = 0.f;
#pragma unroll
        for (int nt = 0; nt < 8; nt++) {
            sc[nt][0] = __expf(sc[nt][0] - mn0);
            sc[nt][1] = __expf(sc[nt][1] - mn0);
            sc[nt][2] = __expf(sc[nt][2] - mn1);
            sc[nt][3] = __expf(sc[nt][3] - mn1);
            rs0 += sc[nt][0] + sc[nt][1];
            rs1 += sc[nt][2] + sc[nt][3];
        }
#pragma unroll
        for (int off = 1; off <= 2; off <<= 1) {
            rs0 += __shfl_xor_sync(0xffffffffu, rs0, off);
            rs1 += __shfl_xor_sync(0xffffffffu, rs1, off);
        }
        li[0] = li[0] * al0 + rs0;
        li[1] = li[1] * al1 + rs1;
#pragma unroll
        for (int nt = 0; nt < 8; nt++) {
            of[nt][0] *= al0; of[nt][1] *= al0;
            of[nt][2] *= al1; of[nt][3] *= al1;
        }

        __syncthreads();  // all warps finished reading Ks before P overwrite
#pragma unroll
        for (int nt = 0; nt < 8; nt++) {
            float* p0 = &KP[(wp * 16 + g) * AST + nt * 8 + tg * 2];
            p0[0] = f2tf(sc[nt][0]);
            p0[1] = f2tf(sc[nt][1]);
            float* p1 = &KP[(wp * 16 + g + 8) * AST + nt * 8 + tg * 2];
            p1[0] = f2tf(sc[nt][2]);
            p1[1] = f2tf(sc[nt][3]);
        }
        __syncthreads();

        // O += P V
#pragma unroll
        for (int kk = 0; kk < 8; kk++) {
            const int k = kk * 8;
            const float* ap = &KP[(wp * 16 + g) * AST + k + tg];
            unsigned a0 = FB(ap[0]), a1 = FB(ap[8 * AST]);
            unsigned a2 = FB(ap[4]), a3 = FB(ap[8 * AST + 4]);
#pragma unroll
            for (int nt = 0; nt < 8; nt++) {
                const float* bp = &Vs[(nt * 8 + g) * AST + k + tg];
                mma_tf32(of[nt], a0, a1, a2, a3, FB(bp[0]), FB(bp[4]));
            }
        }
    }

    // Epilogue: normalize, write g_AO [b, n, h*64 + d]
    const int b = bh >> 4;
    const int h = bh & 15;
    const float inv0 = 1.0f / li[0];
    const float inv1 = 1.0f / li[1];
    const int row0 = q0 + wp * 16 + g;
#pragma unroll
    for (int nt = 0; nt < 8; nt++) {
        int d = nt * 8 + tg * 2;
        *(float2*)&g_AO[((size_t)(b * SEQ + row0)) * DINNER + h * 64 + d] =
            make_float2(of[nt][0] * inv0, of[nt][1] * inv0);
        *(float2*)&g_AO[((size_t)(b * SEQ + row0 + 8)) * DINNER + h * 64 + d] =
            make_float2(of[nt][2] * inv1, of[nt][3] * inv1);
    }
}

// ---------------------------------------------------------------------------
extern "C" void kernel_launch(void* const* d_in, const int* in_sizes, int n_in,
                              void* d_out, int out_size) {
    const float* x     = (const float*)d_in[0];
    const float* w_qkv = (const float*)d_in[1];
    const float* w_out = (const float*)d_in[2];
    const float* b_out = (const float*)d_in[3];
    float* out = (float*)d_out;

    cudaFuncSetAttribute(attn_kernel, cudaFuncAttributeMaxDynamicSharedMemorySize,
                         ATTN_SMEM_BYTES);

    qkv_gemm<<<dim3(NQKV / 128, MROWS / 128), 256>>>(x, w_qkv);
    attn_kernel<<<dim3(SEQ / 128, BATCH * HEADS), 256, ATTN_SMEM_BYTES>>>();
    out_gemm<<<dim3(DSEQ / 128, MROWS / 128), 256>>>(w_out, b_out, out);
}

// round 5
// speedup vs baseline: 3.0878x; 1.1795x over previous
#include <cuda_runtime.h>

#define BATCH 4
#define SEQ   2048
#define DSEQ  1024
#define HEADS 16
#define DHEAD 64
#define DINNER 1024
#define MROWS (BATCH*SEQ)   // 8192
#define NQKV  (3*DINNER)    // 3072

// Scratch (allocation-free: __device__ globals)
__device__ float g_Q[BATCH * HEADS * SEQ * DHEAD];
__device__ float g_K[BATCH * HEADS * SEQ * DHEAD];
__device__ float g_V[BATCH * HEADS * SEQ * DHEAD];
__device__ float g_AO[MROWS * DINNER];

__device__ __forceinline__ float f2tf(float f) {
    unsigned u;
    asm("cvt.rna.tf32.f32 %0, %1;" : "=r"(u) : "f"(f));
    return __uint_as_float(u);
}
__device__ __forceinline__ void mma_tf32(float c[4],
                                         unsigned a0, unsigned a1, unsigned a2, unsigned a3,
                                         unsigned b0, unsigned b1) {
    asm volatile(
        "mma.sync.aligned.m16n8k8.row.col.f32.tf32.tf32.f32 "
        "{%0,%1,%2,%3},{%4,%5,%6,%7},{%8,%9},{%0,%1,%2,%3};"
        : "+f"(c[0]), "+f"(c[1]), "+f"(c[2]), "+f"(c[3])
        : "r"(a0), "r"(a1), "r"(a2), "r"(a3), "r"(b0), "r"(b1));
}
#define FB(x) __float_as_uint(x)

// ---------------------------------------------------------------------
// GEMM: D = A[M,1024] @ B[N,1024]^T. BM=BN=128, BK=16, 8 warps (2m x 4n),
// warp tile 64x32. Row-major smem, stride GST=20 -> fragment reads
// conflict-free ((20g+tg) mod 32 covers all banks). 2-stage double buffer,
// register prefetch, one barrier per k-tile.
// mode 0: A = Aarg (x), scatter to g_Q/g_K/g_V.
// mode 1: A = g_AO (resolved IN DEVICE CODE), out = D + bias.
// ---------------------------------------------------------------------
#define GST 20

__device__ __forceinline__ void g_store_tile(float* As_, float* Bs_,
                                             float4 av0, float4 av1,
                                             float4 bv0, float4 bv1,
                                             int lrow, int lk) {
    *(float4*)&As_[lrow * GST + lk] =
        make_float4(f2tf(av0.x), f2tf(av0.y), f2tf(av0.z), f2tf(av0.w));
    *(float4*)&As_[lrow * GST + lk + 4] =
        make_float4(f2tf(av1.x), f2tf(av1.y), f2tf(av1.z), f2tf(av1.w));
    *(float4*)&Bs_[lrow * GST + lk] =
        make_float4(f2tf(bv0.x), f2tf(bv0.y), f2tf(bv0.z), f2tf(bv0.w));
    *(float4*)&Bs_[lrow * GST + lk + 4] =
        make_float4(f2tf(bv1.x), f2tf(bv1.y), f2tf(bv1.z), f2tf(bv1.w));
}

__device__ __forceinline__ void g_mma_tile(const float* As_, const float* Bs_,
                                           float c[4][4][4],
                                           int wm, int wn, int g, int tg) {
#pragma unroll
    for (int kk = 0; kk < 2; kk++) {
        const int k = kk * 8;
        unsigned a[4][4], b[4][2];
#pragma unroll
        for (int mt = 0; mt < 4; mt++) {
            const float* ap = &As_[(wm * 64 + mt * 16 + g) * GST + k + tg];
            a[mt][0] = FB(ap[0]);
            a[mt][1] = FB(ap[8 * GST]);
            a[mt][2] = FB(ap[4]);
            a[mt][3] = FB(ap[8 * GST + 4]);
        }
#pragma unroll
        for (int nt = 0; nt < 4; nt++) {
            const float* bp = &Bs_[(wn * 32 + nt * 8 + g) * GST + k + tg];
            b[nt][0] = FB(bp[0]);
            b[nt][1] = FB(bp[4]);
        }
#pragma unroll
        for (int mt = 0; mt < 4; mt++)
#pragma unroll
            for (int nt = 0; nt < 4; nt++)
                mma_tf32(c[mt][nt], a[mt][0], a[mt][1], a[mt][2], a[mt][3],
                         b[nt][0], b[nt][1]);
    }
}

__global__ __launch_bounds__(256, 2) void gemm_kernel(
    const float* __restrict__ Aarg, const float* __restrict__ B,
    const float* __restrict__ bias, float* __restrict__ out, int mode)
{
    __shared__ float As[2][128 * GST];
    __shared__ float Bs[2][128 * GST];

    const int t    = threadIdx.x;
    const int lane = t & 31;
    const int wp   = t >> 5;
    const int g    = lane >> 2;
    const int tg   = lane & 3;
    const int wm   = wp & 1;
    const int wn   = wp >> 1;
    const int m0   = blockIdx.y * 128;
    const int n0   = blockIdx.x * 128;

    // Resolve A in DEVICE code (host cannot take &g_AO).
    const float* A = (mode == 1) ? (const float*)g_AO : Aarg;

    const int lrow = t >> 1;
    const int lk   = (t & 1) * 8;
    const float* Ag = A + (size_t)(m0 + lrow) * 1024 + lk;
    const float* Bg = B + (size_t)(n0 + lrow) * 1024 + lk;

    float4 av0 = *(const float4*)(Ag);
    float4 av1 = *(const float4*)(Ag + 4);
    float4 bv0 = *(const float4*)(Bg);
    float4 bv1 = *(const float4*)(Bg + 4);

    float c[4][4][4] = {};
    int cur = 0;

    g_store_tile(As[0], Bs[0], av0, av1, bv0, bv1, lrow, lk);
    __syncthreads();

    for (int k0 = 16; k0 < 1024; k0 += 16) {
        av0 = *(const float4*)(Ag + k0);
        av1 = *(const float4*)(Ag + k0 + 4);
        bv0 = *(const float4*)(Bg + k0);
        bv1 = *(const float4*)(Bg + k0 + 4);
        g_mma_tile(As[cur], Bs[cur], c, wm, wn, g, tg);
        g_store_tile(As[cur ^ 1], Bs[cur ^ 1], av0, av1, bv0, bv1, lrow, lk);
        __syncthreads();
        cur ^= 1;
    }
    g_mma_tile(As[cur], Bs[cur], c, wm, wn, g, tg);

    if (mode == 0) {
#pragma unroll
        for (int mt = 0; mt < 4; mt++) {
#pragma unroll
            for (int nt = 0; nt < 4; nt++) {
                int col  = n0 + wn * 32 + nt * 8 + tg * 2;
                int part = col >> 10;
                int h    = (col >> 6) & 15;
                int d    = col & 63;
                float* Tp = (part == 0) ? g_Q : (part == 1) ? g_K : g_V;
                int m  = m0 + wm * 64 + mt * 16 + g;
                int b  = m >> 11, n = m & 2047;
                *(float2*)&Tp[(((size_t)(b * HEADS + h)) * SEQ + n) * DHEAD + d] =
                    make_float2(c[mt][nt][0], c[mt][nt][1]);
                int m2 = m + 8;
                int b2 = m2 >> 11, n2 = m2 & 2047;
                *(float2*)&Tp[(((size_t)(b2 * HEADS + h)) * SEQ + n2) * DHEAD + d] =
                    make_float2(c[mt][nt][2], c[mt][nt][3]);
            }
        }
    } else {
#pragma unroll
        for (int mt = 0; mt < 4; mt++) {
#pragma unroll
            for (int nt = 0; nt < 4; nt++) {
                int col = n0 + wn * 32 + nt * 8 + tg * 2;
                float bx = bias[col], by = bias[col + 1];
                int m = m0 + wm * 64 + mt * 16 + g;
                *(float2*)&out[(size_t)m * DSEQ + col] =
                    make_float2(c[mt][nt][0] + bx, c[mt][nt][1] + by);
                *(float2*)&out[(size_t)(m + 8) * DSEQ + col] =
                    make_float2(c[mt][nt][2] + bx, c[mt][nt][3] + by);
            }
        }
    }
}

// ---------------------------------------------------------------------
// Flash attention (round-2 layouts; conflict-free reads).
// Q-tile 128, KV-tile 64. 8 warps stacked in m (16 rows each).
// Qs[128][68] (m,d) | Ks[64][68] (j,d) | Vs[64][68] (d,j) | Ps[128][68] (m,j)
// Per-warp P rows are warp-private -> syncwarp instead of barrier.
// Next K/V prefetched into registers during softmax/PV.
// ---------------------------------------------------------------------
#define AST 68
#define ATTN_FLOATS ((128 + 64 + 64 + 128) * AST)
#define ATTN_SMEM_BYTES (ATTN_FLOATS * 4)

__global__ __launch_bounds__(256, 2) void attn_kernel() {
    extern __shared__ float sm[];
    float* Qs = sm;                       // 128*AST
    float* Ks = sm + 128 * AST;           // 64*AST
    float* Vs = sm + 192 * AST;           // 64*AST (transposed [d][j])
    float* Ps = sm + 256 * AST;           // 128*AST

    const int t    = threadIdx.x;
    const int lane = t & 31;
    const int wp   = t >> 5;
    const int g    = lane >> 2;
    const int tg   = lane & 3;
    const int bh   = blockIdx.y;
    const int q0   = blockIdx.x * 128;

    const size_t base = (size_t)bh * SEQ * DHEAD;
    const float* Qg = g_Q + base;
    const float* Kg = g_K + base;
    const float* Vg = g_V + base;

    // ---- load Q tile (pre-scaled, tf32-rounded), vectorized ----
    {
        int row = t >> 1, h0 = (t & 1) * 32;
        const float* src = Qg + (size_t)(q0 + row) * DHEAD + h0;
        float* dst = &Qs[row * AST + h0];
#pragma unroll
        for (int i = 0; i < 8; i++) {
            float4 v = *(const float4*)(src + i * 4);
            *(float4*)(dst + i * 4) = make_float4(
                f2tf(v.x * 0.125f), f2tf(v.y * 0.125f),
                f2tf(v.z * 0.125f), f2tf(v.w * 0.125f));
        }
    }

    const int j   = t >> 2;          // 0..63
    const int seg = (t & 3) * 16;

    float4 pk[4], pv[4];
    {
        const float* ksrc = Kg + (size_t)j * DHEAD + seg;
        const float* vsrc = Vg + (size_t)j * DHEAD + seg;
#pragma unroll
        for (int i = 0; i < 4; i++) {
            pk[i] = *(const float4*)(ksrc + i * 4);
            pv[i] = *(const float4*)(vsrc + i * 4);
        }
    }

    float mi[2] = {-1e30f, -1e30f};
    float li[2] = {0.f, 0.f};
    float of[8][4] = {};

    for (int kv0 = 0; kv0 < SEQ; kv0 += 64) {
        // ---- store prefetched K/V tiles ----
        {
            float* kd = &Ks[j * AST + seg];
#pragma unroll
            for (int i = 0; i < 4; i++) {
                *(float4*)(kd + i * 4) = make_float4(
                    f2tf(pk[i].x), f2tf(pk[i].y), f2tf(pk[i].z), f2tf(pk[i].w));
                float e[4] = {pv[i].x, pv[i].y, pv[i].z, pv[i].w};
#pragma unroll
                for (int ee = 0; ee < 4; ee++)
                    Vs[(seg + i * 4 + ee) * AST + j] = f2tf(e[ee]);
            }
        }
        __syncthreads();   // K/V (and Q on iter 0) visible

        // ---- S = Q K^T ----
        float sc[8][4] = {};
#pragma unroll
        for (int kk = 0; kk < 8; kk++) {
            const int k = kk * 8;
            const float* ap = &Qs[(wp * 16 + g) * AST + k + tg];
            unsigned a0 = FB(ap[0]), a1 = FB(ap[8 * AST]);
            unsigned a2 = FB(ap[4]), a3 = FB(ap[8 * AST + 4]);
#pragma unroll
            for (int nt = 0; nt < 8; nt++) {
                const float* bp = &Ks[(nt * 8 + g) * AST + k + tg];
                mma_tf32(sc[nt], a0, a1, a2, a3, FB(bp[0]), FB(bp[4]));
            }
        }

        // ---- online softmax ----
        float mx0 = -1e30f, mx1 = -1e30f;
#pragma unroll
        for (int nt = 0; nt < 8; nt++) {
            mx0 = fmaxf(mx0, fmaxf(sc[nt][0], sc[nt][1]));
            mx1 = fmaxf(mx1, fmaxf(sc[nt][2], sc[nt][3]));
        }
#pragma unroll
        for (int off = 1; off <= 2; off <<= 1) {
            mx0 = fmaxf(mx0, __shfl_xor_sync(0xffffffffu, mx0, off));
            mx1 = fmaxf(mx1, __shfl_xor_sync(0xffffffffu, mx1, off));
        }
        float mn0 = fmaxf(mi[0], mx0), mn1 = fmaxf(mi[1], mx1);
        float al0 = __expf(mi[0] - mn0), al1 = __expf(mi[1] - mn1);
        mi[0] = mn0; mi[1] = mn1;
        float rs0 = 0.f, rs1 = 0.f;
#pragma unroll
        for (int nt = 0; nt < 8; nt++) {
            sc[nt][0] = __expf(sc[nt][0] - mn0);
            sc[nt][1] = __expf(sc[nt][1] - mn0);
            sc[nt][2] = __expf(sc[nt][2] - mn1);
            sc[nt][3] = __expf(sc[nt][3] - mn1);
            rs0 += sc[nt][0] + sc[nt][1];
            rs1 += sc[nt][2] + sc[nt][3];
        }
#pragma unroll
        for (int off = 1; off <= 2; off <<= 1) {
            rs0 += __shfl_xor_sync(0xffffffffu, rs0, off);
            rs1 += __shfl_xor_sync(0xffffffffu, rs1, off);
        }
        li[0] = li[0] * al0 + rs0;
        li[1] = li[1] * al1 + rs1;
#pragma unroll
        for (int nt = 0; nt < 8; nt++) {
            of[nt][0] *= al0; of[nt][1] *= al0;
            of[nt][2] *= al1; of[nt][3] *= al1;
        }

        // ---- store P (warp-private rows) ----
#pragma unroll
        for (int nt = 0; nt < 8; nt++) {
            *(float2*)&Ps[(wp * 16 + g) * AST + nt * 8 + tg * 2] =
                make_float2(f2tf(sc[nt][0]), f2tf(sc[nt][1]));
            *(float2*)&Ps[(wp * 16 + g + 8) * AST + nt * 8 + tg * 2] =
                make_float2(f2tf(sc[nt][2]), f2tf(sc[nt][3]));
        }
        __syncwarp();

        // ---- prefetch next K/V tile (latency hidden under PV) ----
        {
            int kvn = (kv0 + 64 < SEQ) ? kv0 + 64 : 0;
            const float* ksrc = Kg + (size_t)(kvn + j) * DHEAD + seg;
            const float* vsrc = Vg + (size_t)(kvn + j) * DHEAD + seg;
#pragma unroll
            for (int i = 0; i < 4; i++) {
                pk[i] = *(const float4*)(ksrc + i * 4);
                pv[i] = *(const float4*)(vsrc + i * 4);
            }
        }

        // ---- O += P V ----
#pragma unroll
        for (int kk = 0; kk < 8; kk++) {
            const int k = kk * 8;
            const float* ap = &Ps[(wp * 16 + g) * AST + k + tg];
            unsigned a0 = FB(ap[0]), a1 = FB(ap[8 * AST]);
            unsigned a2 = FB(ap[4]), a3 = FB(ap[8 * AST + 4]);
#pragma unroll
            for (int nt = 0; nt < 8; nt++) {
                const float* bp = &Vs[(nt * 8 + g) * AST + k + tg];
                mma_tf32(of[nt], a0, a1, a2, a3, FB(bp[0]), FB(bp[4]));
            }
        }
        __syncthreads();   // all S/PV reads of Ks/Vs done before next store
    }

    // ---- epilogue ----
    const int b = bh >> 4;
    const int h = bh & 15;
    const float inv0 = 1.0f / li[0];
    const float inv1 = 1.0f / li[1];
    const int row0 = q0 + wp * 16 + g;
#pragma unroll
    for (int nt = 0; nt < 8; nt++) {
        int d = nt * 8 + tg * 2;
        *(float2*)&g_AO[((size_t)(b * SEQ + row0)) * DINNER + h * 64 + d] =
            make_float2(of[nt][0] * inv0, of[nt][1] * inv0);
        *(float2*)&g_AO[((size_t)(b * SEQ + row0 + 8)) * DINNER + h * 64 + d] =
            make_float2(of[nt][2] * inv1, of[nt][3] * inv1);
    }
}

// ---------------------------------------------------------------------
extern "C" void kernel_launch(void* const* d_in, const int* in_sizes, int n_in,
                              void* d_out, int out_size) {
    const float* x     = (const float*)d_in[0];
    const float* w_qkv = (const float*)d_in[1];
    const float* w_out = (const float*)d_in[2];
    const float* b_out = (const float*)d_in[3];
    float* out = (float*)d_out;

    cudaFuncSetAttribute(attn_kernel, cudaFuncAttributeMaxDynamicSharedMemorySize,
                         ATTN_SMEM_BYTES);

    gemm_kernel<<<dim3(NQKV / 128, MROWS / 128), 256>>>(x, w_qkv, nullptr, nullptr, 0);
    attn_kernel<<<dim3(SEQ / 128, BATCH * HEADS), 256, ATTN_SMEM_BYTES>>>();
    gemm_kernel<<<dim3(DSEQ / 128, MROWS / 128), 256>>>(nullptr, w_out, b_out, out, 1);
}

// round 7
// speedup vs baseline: 3.1900x; 1.0331x over previous
#include <cuda_runtime.h>
#include <cstdint>

#define BATCH 4
#define SEQ   2048
#define DSEQ  1024
#define HEADS 16
#define DHEAD 64
#define DINNER 1024
#define MROWS (BATCH*SEQ)   // 8192
#define NQKV  (3*DINNER)    // 3072

// Scratch (allocation-free: __device__ globals)
__device__ float g_Q[BATCH * HEADS * SEQ * DHEAD];
__device__ float g_K[BATCH * HEADS * SEQ * DHEAD];
__device__ float g_V[BATCH * HEADS * SEQ * DHEAD];
__device__ float g_AO[MROWS * DINNER];

__device__ __forceinline__ float f2tf(float f) {
    unsigned u;
    asm("cvt.rna.tf32.f32 %0, %1;" : "=r"(u) : "f"(f));
    return __uint_as_float(u);
}
__device__ __forceinline__ void mma_tf32(float c[4],
                                         unsigned a0, unsigned a1, unsigned a2, unsigned a3,
                                         unsigned b0, unsigned b1) {
    asm volatile(
        "mma.sync.aligned.m16n8k8.row.col.f32.tf32.tf32.f32 "
        "{%0,%1,%2,%3},{%4,%5,%6,%7},{%8,%9},{%0,%1,%2,%3};"
        : "+f"(c[0]), "+f"(c[1]), "+f"(c[2]), "+f"(c[3])
        : "r"(a0), "r"(a1), "r"(a2), "r"(a3), "r"(b0), "r"(b1));
}
#define FB(x) __float_as_uint(x)

__device__ __forceinline__ unsigned smem_u32(const void* p) {
    unsigned a;
    asm("{ .reg .u64 t; cvta.to.shared.u64 t, %1; cvt.u32.u64 %0, t; }"
        : "=r"(a) : "l"(p));
    return a;
}
__device__ __forceinline__ void cp16(unsigned dst, const float* src) {
    asm volatile("cp.async.cg.shared.global [%0], [%1], 16;"
                 :: "r"(dst), "l"(src) : "memory");
}
#define CP_COMMIT() asm volatile("cp.async.commit_group;" ::: "memory")
#define CP_WAIT2()  asm volatile("cp.async.wait_group 2;" ::: "memory")

// ---------------------------------------------------------------------
// GEMM: D = A[M,1024] @ B[N,1024]^T. BM=BN=128, BK=16, 8 warps (2m x 4n),
// warp tile 64x32. Row-major smem stride GST=20 (fragment reads conflict-
// free). 4-stage cp.async pipeline, tf32 conversion at fragment load.
// mode 0: A = x, scatter to g_Q/g_K/g_V.
// mode 1: A = g_AO (device-resolved), out = D + bias.
// ---------------------------------------------------------------------
#define GST 20
#define NSTG 4
#define STGF (128 * GST)          // floats per matrix per stage
#define GNIT 64                   // 1024 / 16
#define GEMM_SMEM_BYTES (2 * NSTG * STGF * 4)   // 81920

__device__ __forceinline__ void g_mma_tile(const float* As_, const float* Bs_,
                                           float c[4][4][4],
                                           int wm, int wn, int g, int tg) {
#pragma unroll
    for (int kk = 0; kk < 2; kk++) {
        const int k = kk * 8;
        unsigned a[4][4], b[4][2];
#pragma unroll
        for (int mt = 0; mt < 4; mt++) {
            const float* ap = &As_[(wm * 64 + mt * 16 + g) * GST + k + tg];
            a[mt][0] = FB(f2tf(ap[0]));
            a[mt][1] = FB(f2tf(ap[8 * GST]));
            a[mt][2] = FB(f2tf(ap[4]));
            a[mt][3] = FB(f2tf(ap[8 * GST + 4]));
        }
#pragma unroll
        for (int nt = 0; nt < 4; nt++) {
            const float* bp = &Bs_[(wn * 32 + nt * 8 + g) * GST + k + tg];
            b[nt][0] = FB(f2tf(bp[0]));
            b[nt][1] = FB(f2tf(bp[4]));
        }
#pragma unroll
        for (int mt = 0; mt < 4; mt++)
#pragma unroll
            for (int nt = 0; nt < 4; nt++)
                mma_tf32(c[mt][nt], a[mt][0], a[mt][1], a[mt][2], a[mt][3],
                         b[nt][0], b[nt][1]);
    }
}

__global__ __launch_bounds__(256, 2) void gemm_kernel(
    const float* __restrict__ Aarg, const float* __restrict__ B,
    const float* __restrict__ bias, float* __restrict__ out, int mode)
{
    extern __shared__ float smf[];
    float* As = smf;                 // NSTG stages
    float* Bs = smf + NSTG * STGF;

    const int t    = threadIdx.x;
    const int lane = t & 31;
    const int wp   = t >> 5;
    const int g    = lane >> 2;
    const int tg   = lane & 3;
    const int wm   = wp & 1;
    const int wn   = wp >> 1;
    const int m0   = blockIdx.y * 128;
    const int n0   = blockIdx.x * 128;

    const float* A = (mode == 1) ? (const float*)g_AO : Aarg;

    // loader: thread t -> row t>>1, 8-float half (t&1)*8; 2x cp16 per matrix
    const int row  = t >> 1;
    const int half = (t & 1) * 8;
    const float* Ag = A + (size_t)(m0 + row) * 1024 + half;
    const float* Bg = B + (size_t)(n0 + row) * 1024 + half;
    const unsigned aOff = smem_u32(As) + (unsigned)(row * GST + half) * 4u;
    const unsigned bOff = smem_u32(Bs) + (unsigned)(row * GST + half) * 4u;

    // prologue: stages 0..2 in flight
#pragma unroll
    for (int s = 0; s < 3; s++) {
        const int k0 = s * 16;
        const unsigned so = (unsigned)(s * STGF) * 4u;
        cp16(aOff + so,      Ag + k0);
        cp16(aOff + so + 16, Ag + k0 + 4);
        cp16(bOff + so,      Bg + k0);
        cp16(bOff + so + 16, Bg + k0 + 4);
        CP_COMMIT();
    }

    float c[4][4][4] = {};

    for (int it = 0; it < GNIT; it++) {
        CP_WAIT2();          // stage `it` complete (3 groups always outstanding)
        __syncthreads();     // all warps done with buffer (it+3)%4's previous use
        if (it + 3 < GNIT) {
            const int k0 = (it + 3) * 16;
            const unsigned so = (unsigned)(((it + 3) & 3) * STGF) * 4u;
            cp16(aOff + so,      Ag + k0);
            cp16(aOff + so + 16, Ag + k0 + 4);
            cp16(bOff + so,      Bg + k0);
            cp16(bOff + so + 16, Bg + k0 + 4);
        }
        CP_COMMIT();         // always commit (possibly empty) to keep count fixed
        const int cs = (it & 3) * STGF;
        g_mma_tile(As + cs, Bs + cs, c, wm, wn, g, tg);
    }

    if (mode == 0) {
#pragma unroll
        for (int mt = 0; mt < 4; mt++) {
#pragma unroll
            for (int nt = 0; nt < 4; nt++) {
                int col  = n0 + wn * 32 + nt * 8 + tg * 2;
                int part = col >> 10;
                int h    = (col >> 6) & 15;
                int d    = col & 63;
                float* Tp = (part == 0) ? g_Q : (part == 1) ? g_K : g_V;
                int m  = m0 + wm * 64 + mt * 16 + g;
                int b  = m >> 11, n = m & 2047;
                *(float2*)&Tp[(((size_t)(b * HEADS + h)) * SEQ + n) * DHEAD + d] =
                    make_float2(c[mt][nt][0], c[mt][nt][1]);
                int m2 = m + 8;
                int b2 = m2 >> 11, n2 = m2 & 2047;
                *(float2*)&Tp[(((size_t)(b2 * HEADS + h)) * SEQ + n2) * DHEAD + d] =
                    make_float2(c[mt][nt][2], c[mt][nt][3]);
            }
        }
    } else {
#pragma unroll
        for (int mt = 0; mt < 4; mt++) {
#pragma unroll
            for (int nt = 0; nt < 4; nt++) {
                int col = n0 + wn * 32 + nt * 8 + tg * 2;
                float bx = bias[col], by = bias[col + 1];
                int m = m0 + wm * 64 + mt * 16 + g;
                *(float2*)&out[(size_t)m * DSEQ + col] =
                    make_float2(c[mt][nt][0] + bx, c[mt][nt][1] + by);
                *(float2*)&out[(size_t)(m + 8) * DSEQ + col] =
                    make_float2(c[mt][nt][2] + bx, c[mt][nt][3] + by);
            }
        }
    }
}

// ---------------------------------------------------------------------
// Flash attention (round-5, verified; unchanged).
// ---------------------------------------------------------------------
#define AST 68
#define ATTN_FLOATS ((128 + 64 + 64 + 128) * AST)
#define ATTN_SMEM_BYTES (ATTN_FLOATS * 4)

__global__ __launch_bounds__(256, 2) void attn_kernel() {
    extern __shared__ float sm[];
    float* Qs = sm;
    float* Ks = sm + 128 * AST;
    float* Vs = sm + 192 * AST;
    float* Ps = sm + 256 * AST;

    const int t    = threadIdx.x;
    const int lane = t & 31;
    const int wp   = t >> 5;
    const int g    = lane >> 2;
    const int tg   = lane & 3;
    const int bh   = blockIdx.y;
    const int q0   = blockIdx.x * 128;

    const size_t base = (size_t)bh * SEQ * DHEAD;
    const float* Qg = g_Q + base;
    const float* Kg = g_K + base;
    const float* Vg = g_V + base;

    {
        int row = t >> 1, h0 = (t & 1) * 32;
        const float* src = Qg + (size_t)(q0 + row) * DHEAD + h0;
        float* dst = &Qs[row * AST + h0];
#pragma unroll
        for (int i = 0; i < 8; i++) {
            float4 v = *(const float4*)(src + i * 4);
            *(float4*)(dst + i * 4) = make_float4(
                f2tf(v.x * 0.125f), f2tf(v.y * 0.125f),
                f2tf(v.z * 0.125f), f2tf(v.w * 0.125f));
        }
    }

    const int j   = t >> 2;
    const int seg = (t & 3) * 16;

    float4 pk[4], pv[4];
    {
        const float* ksrc = Kg + (size_t)j * DHEAD + seg;
        const float* vsrc = Vg + (size_t)j * DHEAD + seg;
#pragma unroll
        for (int i = 0; i < 4; i++) {
            pk[i] = *(const float4*)(ksrc + i * 4);
            pv[i] = *(const float4*)(vsrc + i * 4);
        }
    }

    float mi[2] = {-1e30f, -1e30f};
    float li[2] = {0.f, 0.f};
    float of[8][4] = {};

    for (int kv0 = 0; kv0 < SEQ; kv0 += 64) {
        {
            float* kd = &Ks[j * AST + seg];
#pragma unroll
            for (int i = 0; i < 4; i++) {
                *(float4*)(kd + i * 4) = make_float4(
                    f2tf(pk[i].x), f2tf(pk[i].y), f2tf(pk[i].z), f2tf(pk[i].w));
                float e[4] = {pv[i].x, pv[i].y, pv[i].z, pv[i].w};
#pragma unroll
                for (int ee = 0; ee < 4; ee++)
                    Vs[(seg + i * 4 + ee) * AST + j] = f2tf(e[ee]);
            }
        }
        __syncthreads();

        float sc[8][4] = {};
#pragma unroll
        for (int kk = 0; kk < 8; kk++) {
            const int k = kk * 8;
            const float* ap = &Qs[(wp * 16 + g) * AST + k + tg];
            unsigned a0 = FB(ap[0]), a1 = FB(ap[8 * AST]);
            unsigned a2 = FB(ap[4]), a3 = FB(ap[8 * AST + 4]);
#pragma unroll
            for (int nt = 0; nt < 8; nt++) {
                const float* bp = &Ks[(nt * 8 + g) * AST + k + tg];
                mma_tf32(sc[nt], a0, a1, a2, a3, FB(bp[0]), FB(bp[4]));
            }
        }

        float mx0 = -1e30f, mx1 = -1e30f;
#pragma unroll
        for (int nt = 0; nt < 8; nt++) {
            mx0 = fmaxf(mx0, fmaxf(sc[nt][0], sc[nt][1]));
            mx1 = fmaxf(mx1, fmaxf(sc[nt][2], sc[nt][3]));
        }
#pragma unroll
        for (int off = 1; off <= 2; off <<= 1) {
            mx0 = fmaxf(mx0, __shfl_xor_sync(0xffffffffu, mx0, off));
            mx1 = fmaxf(mx1, __shfl_xor_sync(0xffffffffu, mx1, off));
        }
        float mn0 = fmaxf(mi[0], mx0), mn1 = fmaxf(mi[1], mx1);
        float al0 = __expf(mi[0] - mn0), al1 = __expf(mi[1] - mn1);
        mi[0] = mn0; mi[1] = mn1;
        float rs0 = 0.f, rs1 = 0.f;
#pragma unroll
        for (int nt = 0; nt < 8; nt++) {
            sc[nt][0] = __expf(sc[nt][0] - mn0);
            sc[nt][1] = __expf(sc[nt][1] - mn0);
            sc[nt][2] = __expf(sc[nt][2] - mn1);
            sc[nt][3] = __expf(sc[nt][3] - mn1);
            rs0 += sc[nt][0] + sc[nt][1];
            rs1 += sc[nt][2] + sc[nt][3];
        }
#pragma unroll
        for (int off = 1; off <= 2; off <<= 1) {
            rs0 += __shfl_xor_sync(0xffffffffu, rs0, off);
            rs1 += __shfl_xor_sync(0xffffffffu, rs1, off);
        }
        li[0] = li[0] * al0 + rs0;
        li[1] = li[1] * al1 + rs1;
#pragma unroll
        for (int nt = 0; nt < 8; nt++) {
            of[nt][0] *= al0; of[nt][1] *= al0;
            of[nt][2] *= al1; of[nt][3] *= al1;
        }

#pragma unroll
        for (int nt = 0; nt < 8; nt++) {
            *(float2*)&Ps[(wp * 16 + g) * AST + nt * 8 + tg * 2] =
                make_float2(f2tf(sc[nt][0]), f2tf(sc[nt][1]));
            *(float2*)&Ps[(wp * 16 + g + 8) * AST + nt * 8 + tg * 2] =
                make_float2(f2tf(sc[nt][2]), f2tf(sc[nt][3]));
        }
        __syncwarp();

        {
            int kvn = (kv0 + 64 < SEQ) ? kv0 + 64 : 0;
            const float* ksrc = Kg + (size_t)(kvn + j) * DHEAD + seg;
            const float* vsrc = Vg + (size_t)(kvn + j) * DHEAD + seg;
#pragma unroll
            for (int i = 0; i < 4; i++) {
                pk[i] = *(const float4*)(ksrc + i * 4);
                pv[i] = *(const float4*)(vsrc + i * 4);
            }
        }

#pragma unroll
        for (int kk = 0; kk < 8; kk++) {
            const int k = kk * 8;
            const float* ap = &Ps[(wp * 16 + g) * AST + k + tg];
            unsigned a0 = FB(ap[0]), a1 = FB(ap[8 * AST]);
            unsigned a2 = FB(ap[4]), a3 = FB(ap[8 * AST + 4]);
#pragma unroll
            for (int nt = 0; nt < 8; nt++) {
                const float* bp = &Vs[(nt * 8 + g) * AST + k + tg];
                mma_tf32(of[nt], a0, a1, a2, a3, FB(bp[0]), FB(bp[4]));
            }
        }
        __syncthreads();
    }

    const int b = bh >> 4;
    const int h = bh & 15;
    const float inv0 = 1.0f / li[0];
    const float inv1 = 1.0f / li[1];
    const int row0 = q0 + wp * 16 + g;
#pragma unroll
    for (int nt = 0; nt < 8; nt++) {
        int d = nt * 8 + tg * 2;
        *(float2*)&g_AO[((size_t)(b * SEQ + row0)) * DINNER + h * 64 + d] =
            make_float2(of[nt][0] * inv0, of[nt][1] * inv0);
        *(float2*)&g_AO[((size_t)(b * SEQ + row0 + 8)) * DINNER + h * 64 + d] =
            make_float2(of[nt][2] * inv1, of[nt][3] * inv1);
    }
}

// ---------------------------------------------------------------------
extern "C" void kernel_launch(void* const* d_in, const int* in_sizes, int n_in,
                              void* d_out, int out_size) {
    const float* x     = (const float*)d_in[0];
    const float* w_qkv = (const float*)d_in[1];
    const float* w_out = (const float*)d_in[2];
    const float* b_out = (const float*)d_in[3];
    float* out = (float*)d_out;

    cudaFuncSetAttribute(gemm_kernel, cudaFuncAttributeMaxDynamicSharedMemorySize,
                         GEMM_SMEM_BYTES);
    cudaFuncSetAttribute(attn_kernel, cudaFuncAttributeMaxDynamicSharedMemorySize,
                         ATTN_SMEM_BYTES);

    gemm_kernel<<<dim3(NQKV / 128, MROWS / 128), 256, GEMM_SMEM_BYTES>>>(x, w_qkv, nullptr, nullptr, 0);
    attn_kernel<<<dim3(SEQ / 128, BATCH * HEADS), 256, ATTN_SMEM_BYTES>>>();
    gemm_kernel<<<dim3(DSEQ / 128, MROWS / 128), 256, GEMM_SMEM_BYTES>>>(nullptr, w_out, b_out, out, 1);
}